// round 3
// baseline (speedup 1.0000x reference)
#include <cuda_runtime.h>

#define EPSF 1e-10f

static const int R    = 32;
static const int NB1  = 128;   // gram/apply blocks; also # partial tiles
static const int TILE = 32;    // rows staged per smem tile

__device__ float2 g_scratch[NB1 * R * R];   // 1 MB partial Grams
__device__ float2 g_W[R * R];

typedef unsigned long long u64;

// ---- packed f32x2 helpers (FFMA2 only reachable via PTX) ----
__device__ __forceinline__ u64 pk2(float lo, float hi) {
    u64 r; asm("mov.b64 %0, {%1,%2};" : "=l"(r) : "f"(lo), "f"(hi)); return r;
}
__device__ __forceinline__ float2 upk2(u64 v) {
    float lo, hi; asm("mov.b64 {%0,%1}, %2;" : "=f"(lo), "=f"(hi) : "l"(v));
    return make_float2(lo, hi);
}
__device__ __forceinline__ u64 ffma2(u64 a, u64 b, u64 c) {
    u64 d; asm("fma.rn.f32x2 %0, %1, %2, %3;" : "=l"(d) : "l"(a), "l"(b), "l"(c)); return d;
}
__device__ __forceinline__ u64 fadd2(u64 a, u64 b) {
    u64 d; asm("add.rn.f32x2 %0, %1, %2;" : "=l"(d) : "l"(a), "l"(b)); return d;
}

// ---------------------------------------------------------------------------
// K1: partial Gram, smem-tiled, FFMA2.
// Block b owns 128 rows (4 tiles of 32). 256 threads = 4 m-groups x 64.
// Group layout: 8x8 thread grid, each thread a 4x4 complex tile of G.
// smem per tile row m:
//   a_dup[m][i] = (ar,ar,ai,ai)      (conjugate side, pre-splatted)
//   b_ns [m][j] = (vx,vy,vy,-vx)     (plain side, pre-neg-swapped)
// G[i][j] += conj(x[m][i])*x[m][j]:
//   (re,im) += (ar,ar)*(vx,vy) + (ai,ai)*(vy,-vx)   -> 2 FFMA2
// ---------------------------------------------------------------------------
__global__ void __launch_bounds__(256) gram_kernel(const float2* __restrict__ x) {
    __shared__ __align__(16) char sraw[32 * 1024];
    float4 (*a_dup)[R] = reinterpret_cast<float4(*)[R]>(sraw);          // 16KB
    float4 (*b_ns)[R]  = reinterpret_cast<float4(*)[R]>(sraw + 16384);  // 16KB
    u64* red = reinterpret_cast<u64*>(sraw);  // [3][64][16] = 24KB, reused after compute

    const int tid = threadIdx.x;
    const int b   = blockIdx.x;
    const int mg  = tid >> 6;          // m-group 0..3
    const int t64 = tid & 63;
    const int i0  = (t64 >> 3) * 4;
    const int j0  = (t64 & 7) * 4;

    const int sr = tid >> 3;           // staging row 0..31
    const int sc = (tid & 7) * 4;      // staging col base

    const float2* xb = x + (size_t)b * (128 * R);

    u64 acc[4][4];
    #pragma unroll
    for (int a_ = 0; a_ < 4; ++a_)
        #pragma unroll
        for (int c_ = 0; c_ < 4; ++c_) acc[a_][c_] = 0ull;

    float4 p0 = *(const float4*)(xb + sr * R + sc);
    float4 p1 = *(const float4*)(xb + sr * R + sc + 2);

    for (int t = 0; t < 4; ++t) {
        // stage current tile (splat + neg-swap done once here)
        a_dup[sr][sc + 0] = make_float4(p0.x, p0.x, p0.y, p0.y);
        b_ns [sr][sc + 0] = make_float4(p0.x, p0.y, p0.y, -p0.x);
        a_dup[sr][sc + 1] = make_float4(p0.z, p0.z, p0.w, p0.w);
        b_ns [sr][sc + 1] = make_float4(p0.z, p0.w, p0.w, -p0.z);
        a_dup[sr][sc + 2] = make_float4(p1.x, p1.x, p1.y, p1.y);
        b_ns [sr][sc + 2] = make_float4(p1.x, p1.y, p1.y, -p1.x);
        a_dup[sr][sc + 3] = make_float4(p1.z, p1.z, p1.w, p1.w);
        b_ns [sr][sc + 3] = make_float4(p1.z, p1.w, p1.w, -p1.z);
        __syncthreads();

        if (t < 3) {   // prefetch next tile during compute
            p0 = *(const float4*)(xb + (t + 1) * TILE * R + sr * R + sc);
            p1 = *(const float4*)(xb + (t + 1) * TILE * R + sr * R + sc + 2);
        }

        #pragma unroll
        for (int mm = 0; mm < 8; ++mm) {
            const int m = mg + mm * 4;
            u64 A[4][2], B[4][2];
            #pragma unroll
            for (int d = 0; d < 4; ++d) {
                float4 av = a_dup[m][i0 + d];
                A[d][0] = pk2(av.x, av.y); A[d][1] = pk2(av.z, av.w);
                float4 bv = b_ns[m][j0 + d];
                B[d][0] = pk2(bv.x, bv.y); B[d][1] = pk2(bv.z, bv.w);
            }
            #pragma unroll
            for (int di = 0; di < 4; ++di)
                #pragma unroll
                for (int dj = 0; dj < 4; ++dj) {
                    acc[di][dj] = ffma2(A[di][0], B[dj][0], acc[di][dj]);
                    acc[di][dj] = ffma2(A[di][1], B[dj][1], acc[di][dj]);
                }
        }
        __syncthreads();
    }

    // cross-m-group reduce: groups 1..3 -> smem -> group 0 sums + writes tile
    if (mg > 0) {
        u64* dst = red + ((mg - 1) * 64 + t64) * 16;
        #pragma unroll
        for (int di = 0; di < 4; ++di)
            #pragma unroll
            for (int dj = 0; dj < 4; ++dj) dst[di * 4 + dj] = acc[di][dj];
    }
    __syncthreads();
    if (mg == 0) {
        #pragma unroll
        for (int g = 0; g < 3; ++g) {
            const u64* srcp = red + (g * 64 + t64) * 16;
            #pragma unroll
            for (int di = 0; di < 4; ++di)
                #pragma unroll
                for (int dj = 0; dj < 4; ++dj)
                    acc[di][dj] = fadd2(acc[di][dj], srcp[di * 4 + dj]);
        }
        float4* gout = reinterpret_cast<float4*>(g_scratch + b * (R * R));
        #pragma unroll
        for (int di = 0; di < 4; ++di) {
            float2 c0 = upk2(acc[di][0]), c1 = upk2(acc[di][1]);
            float2 c2 = upk2(acc[di][2]), c3 = upk2(acc[di][3]);
            int base = ((i0 + di) * R + j0) >> 1;
            gout[base]     = make_float4(c0.x, c0.y, c1.x, c1.y);
            gout[base + 1] = make_float4(c2.x, c2.y, c3.x, c3.y);
        }
    }
}

// ---------------------------------------------------------------------------
// K2: reduce + Cholesky + triangular inverse (unchanged from passing version)
// ---------------------------------------------------------------------------
__global__ void solve_kernel() {
    __shared__ float2 As[R * 33];
    __shared__ float4 red[2][512];
    __shared__ float2 colbuf[2][R];

    const int tid = threadIdx.x;
    const int p = tid >> 5, q = tid & 31;

    // ---- Phase A: deterministic reduce of 128 partial tiles ----
    {
        const int pairIdx = tid & 511;
        const int half    = tid >> 9;
        const float4* src = (const float4*)g_scratch;
        float4 s = make_float4(0.f, 0.f, 0.f, 0.f);
        #pragma unroll 16
        for (int bb = 0; bb < NB1 / 2; ++bb) {
            int b = half * (NB1 / 2) + bb;
            float4 a = src[b * 512 + pairIdx];
            s.x += a.x; s.y += a.y; s.z += a.z; s.w += a.w;
        }
        red[half][pairIdx] = s;
    }
    __syncthreads();
    if (tid < 512) {
        float4 u = red[0][tid], v = red[1][tid];
        int e0 = tid * 2, e1 = e0 + 1;
        As[(e0 >> 5) * 33 + (e0 & 31)] = make_float2(u.x + v.x, u.y + v.y);
        As[(e1 >> 5) * 33 + (e1 & 31)] = make_float2(u.z + v.z, u.w + v.w);
    }
    __syncthreads();

    // ---- Phase B: (p,q)-parallel Cholesky ----
    float2 a = As[p * 33 + q];
    for (int k = 0; k < R; ++k) {
        if (q == k) colbuf[k & 1][p] = a;
        __syncthreads();
        float dkk = colbuf[k & 1][k].x;
        float rd  = rsqrtf(dkk + EPSF);
        float d   = (dkk + EPSF) * rd;
        float2 cp = colbuf[k & 1][p];
        float2 cq = colbuf[k & 1][q];
        float2 lp = make_float2(cp.x * rd, cp.y * rd);
        float2 lq = make_float2(cq.x * rd, cq.y * rd);
        if (p > k && q > k) {
            a.x -= lp.x * lq.x + lp.y * lq.y;
            a.y -= lp.y * lq.x - lp.x * lq.y;
        }
        if (q == k) {
            if (p == k)      a = make_float2(d, 0.f);
            else if (p > k)  a = lp;
        }
    }
    __syncthreads();
    As[p * 33 + q] = a;
    __syncthreads();

    // ---- Phase C: warp j solves L^H w = e_j -> W = L^{-H} ----
    {
        const int j    = tid >> 5;
        const int lane = tid & 31;
        const float invd = 1.0f / As[lane * 33 + lane].x;

        float2 accw = make_float2(0.f, 0.f);
        float2 wp   = make_float2(0.f, 0.f);

        for (int qq = j; qq >= 0; --qq) {
            float cre = (((lane == j) ? 1.f : 0.f) - accw.x) * invd;
            float cim = (-accw.y) * invd;
            float wr = __shfl_sync(0xffffffffu, cre, qq);
            float wi = __shfl_sync(0xffffffffu, cim, qq);
            if (lane == qq) { wp.x = wr; wp.y = wi; }

            float2 lqp = As[qq * 33 + lane];
            if (lane < qq) {
                accw.x += lqp.x * wr + lqp.y * wi;
                accw.y += lqp.x * wi - lqp.y * wr;
            }
        }
        g_W[lane * R + j] = wp;   // W[k][j]
    }
}

// ---------------------------------------------------------------------------
// K3: Q = X * W, smem-tiled, FFMA2, k-split across 4 groups + tree reduce.
//   out[m][j] = sum_k x[m][k] * W[k][j]
//   (re,im) += (xr,xr)*(wr,wi) + (xi,xi)*(-wi,wr)   -> 2 FFMA2
// smem: x_dup[m][k] = (xr,xr,xi,xi), Wc[k][j] = (wr,wi,-wi,wr)
// ---------------------------------------------------------------------------
__global__ void __launch_bounds__(256) apply_kernel(const float2* __restrict__ x,
                                                    float2* __restrict__ out) {
    __shared__ float4 x_dup[TILE][R];   // 16KB
    __shared__ float4 Wc[R][R];         // 16KB
    __shared__ u64 redb[2][64 * 16];    // 16KB

    const int tid = threadIdx.x;
    const int b   = blockIdx.x;
    const int kg  = tid >> 6;           // k-group 0..3
    const int t64 = tid & 63;
    const int i0  = (t64 >> 3) * 4;     // row offset in tile
    const int j0  = (t64 & 7) * 4;
    const int k0  = kg * 8;

    const int sr = tid >> 3;
    const int sc = (tid & 7) * 4;

    const float2* xb = x + (size_t)b * (128 * R);
    float4* ob = reinterpret_cast<float4*>(out + (size_t)b * (128 * R));

    // build Wc once
    #pragma unroll
    for (int e4 = 0; e4 < 4; ++e4) {
        int e = tid + e4 * 256;               // e = k*32 + j
        float2 wv = g_W[e];
        Wc[e >> 5][e & 31] = make_float4(wv.x, wv.y, -wv.y, wv.x);
    }

    float4 p0 = *(const float4*)(xb + sr * R + sc);
    float4 p1 = *(const float4*)(xb + sr * R + sc + 2);

    for (int t = 0; t < 4; ++t) {
        x_dup[sr][sc + 0] = make_float4(p0.x, p0.x, p0.y, p0.y);
        x_dup[sr][sc + 1] = make_float4(p0.z, p0.z, p0.w, p0.w);
        x_dup[sr][sc + 2] = make_float4(p1.x, p1.x, p1.y, p1.y);
        x_dup[sr][sc + 3] = make_float4(p1.z, p1.z, p1.w, p1.w);
        __syncthreads();   // also guarantees Wc ready (t=0)

        if (t < 3) {
            p0 = *(const float4*)(xb + (t + 1) * TILE * R + sr * R + sc);
            p1 = *(const float4*)(xb + (t + 1) * TILE * R + sr * R + sc + 2);
        }

        u64 acc[4][4];
        #pragma unroll
        for (int a_ = 0; a_ < 4; ++a_)
            #pragma unroll
            for (int c_ = 0; c_ < 4; ++c_) acc[a_][c_] = 0ull;

        #pragma unroll
        for (int kk = 0; kk < 8; ++kk) {
            const int k = k0 + kk;
            u64 A[4][2], B[4][2];
            #pragma unroll
            for (int d = 0; d < 4; ++d) {
                float4 av = x_dup[i0 + d][k];
                A[d][0] = pk2(av.x, av.y); A[d][1] = pk2(av.z, av.w);
                float4 bv = Wc[k][j0 + d];
                B[d][0] = pk2(bv.x, bv.y); B[d][1] = pk2(bv.z, bv.w);
            }
            #pragma unroll
            for (int di = 0; di < 4; ++di)
                #pragma unroll
                for (int dj = 0; dj < 4; ++dj) {
                    acc[di][dj] = ffma2(A[di][0], B[dj][0], acc[di][dj]);
                    acc[di][dj] = ffma2(A[di][1], B[dj][1], acc[di][dj]);
                }
        }

        // tree reduce across k-groups: (1->0), (3->2), then (2->0)
        __syncthreads();
        if (kg == 1 || kg == 3) {
            u64* dst = redb[kg >> 1] + t64 * 16;
            #pragma unroll
            for (int di = 0; di < 4; ++di)
                #pragma unroll
                for (int dj = 0; dj < 4; ++dj) dst[di * 4 + dj] = acc[di][dj];
        }
        __syncthreads();
        if (kg == 0 || kg == 2) {
            const u64* srcp = redb[kg >> 1] + t64 * 16;
            #pragma unroll
            for (int di = 0; di < 4; ++di)
                #pragma unroll
                for (int dj = 0; dj < 4; ++dj)
                    acc[di][dj] = fadd2(acc[di][dj], srcp[di * 4 + dj]);
        }
        __syncthreads();
        if (kg == 2) {
            u64* dst = redb[0] + t64 * 16;
            #pragma unroll
            for (int di = 0; di < 4; ++di)
                #pragma unroll
                for (int dj = 0; dj < 4; ++dj) dst[di * 4 + dj] = acc[di][dj];
        }
        __syncthreads();
        if (kg == 0) {
            const u64* srcp = redb[0] + t64 * 16;
            #pragma unroll
            for (int di = 0; di < 4; ++di) {
                u64 a0 = fadd2(acc[di][0], srcp[di * 4 + 0]);
                u64 a1 = fadd2(acc[di][1], srcp[di * 4 + 1]);
                u64 a2 = fadd2(acc[di][2], srcp[di * 4 + 2]);
                u64 a3 = fadd2(acc[di][3], srcp[di * 4 + 3]);
                float2 c0 = upk2(a0), c1 = upk2(a1), c2 = upk2(a2), c3 = upk2(a3);
                int base = ((t * TILE + i0 + di) * R + j0) >> 1;
                ob[base]     = make_float4(c0.x, c0.y, c1.x, c1.y);
                ob[base + 1] = make_float4(c2.x, c2.y, c3.x, c3.y);
            }
        }
        __syncthreads();   // protect x_dup/redb before next tile
    }
}

// ---------------------------------------------------------------------------
extern "C" void kernel_launch(void* const* d_in, const int* in_sizes, int n_in,
                              void* d_out, int out_size) {
    const float2* x  = (const float2*)d_in[0];
    float2* out      = (float2*)d_out;

    gram_kernel<<<NB1, 256>>>(x);
    solve_kernel<<<1, 1024>>>();
    apply_kernel<<<NB1, 256>>>(x, out);
}

// round 4
// speedup vs baseline: 1.1278x; 1.1278x over previous
#include <cuda_runtime.h>

#define EPSF 1e-10f

static const int R    = 32;
static const int NBG  = 512;   // gram blocks (32 rows each)
static const int NBR  = 64;    // reduced tile count after stage-2
static const int TILE = 32;

__device__ float2 g_scratch[NBG * R * R];   // 4 MB partial Grams (L2-resident)
__device__ float2 g_red[NBR * R * R];       // 512 KB stage-2 partials
__device__ float2 g_W[R * R];

typedef unsigned long long u64;

// ---- packed f32x2 helpers (FFMA2 only reachable via PTX) ----
__device__ __forceinline__ u64 pk2(float lo, float hi) {
    u64 r; asm("mov.b64 %0, {%1,%2};" : "=l"(r) : "f"(lo), "f"(hi)); return r;
}
__device__ __forceinline__ float2 upk2(u64 v) {
    float lo, hi; asm("mov.b64 {%0,%1}, %2;" : "=f"(lo), "=f"(hi) : "l"(v));
    return make_float2(lo, hi);
}
__device__ __forceinline__ u64 ffma2(u64 a, u64 b, u64 c) {
    u64 d; asm("fma.rn.f32x2 %0, %1, %2, %3;" : "=l"(d) : "l"(a), "l"(b), "l"(c)); return d;
}
__device__ __forceinline__ u64 fadd2(u64 a, u64 b) {
    u64 d; asm("add.rn.f32x2 %0, %1, %2;" : "=l"(d) : "l"(a), "l"(b)); return d;
}

// ---------------------------------------------------------------------------
// K1: partial Gram. 512 blocks x 256 threads, 32 rows per block (one tile).
// 4 m-groups x 64 threads; each thread a 4x4 complex tile of G.
//   a_dup[m][i] = (ar,ar,ai,ai), b_ns[m][j] = (vx,vy,vy,-vx)
//   G[i][j] += conj(x_i)*x_j : 2 FFMA2 per (i,j,m)
// ---------------------------------------------------------------------------
__global__ void __launch_bounds__(256, 3) gram_kernel(const float2* __restrict__ x) {
    __shared__ __align__(16) char sraw[32 * 1024];
    float4 (*a_dup)[R] = reinterpret_cast<float4(*)[R]>(sraw);          // 16KB
    float4 (*b_ns)[R]  = reinterpret_cast<float4(*)[R]>(sraw + 16384);  // 16KB
    u64* red = reinterpret_cast<u64*>(sraw);   // reused after compute (24KB)

    const int tid = threadIdx.x;
    const int b   = blockIdx.x;
    const int mg  = tid >> 6;
    const int t64 = tid & 63;
    const int i0  = (t64 >> 3) * 4;
    const int j0  = (t64 & 7) * 4;

    const int sr = tid >> 3;           // staging row
    const int sc = (tid & 7) * 4;      // staging col base (complex)

    const float2* xb = x + (size_t)b * (TILE * R);

    float4 p0 = *(const float4*)(xb + sr * R + sc);
    float4 p1 = *(const float4*)(xb + sr * R + sc + 2);

    a_dup[sr][sc + 0] = make_float4(p0.x, p0.x, p0.y, p0.y);
    b_ns [sr][sc + 0] = make_float4(p0.x, p0.y, p0.y, -p0.x);
    a_dup[sr][sc + 1] = make_float4(p0.z, p0.z, p0.w, p0.w);
    b_ns [sr][sc + 1] = make_float4(p0.z, p0.w, p0.w, -p0.z);
    a_dup[sr][sc + 2] = make_float4(p1.x, p1.x, p1.y, p1.y);
    b_ns [sr][sc + 2] = make_float4(p1.x, p1.y, p1.y, -p1.x);
    a_dup[sr][sc + 3] = make_float4(p1.z, p1.z, p1.w, p1.w);
    b_ns [sr][sc + 3] = make_float4(p1.z, p1.w, p1.w, -p1.z);
    __syncthreads();

    u64 acc[4][4];
    #pragma unroll
    for (int a_ = 0; a_ < 4; ++a_)
        #pragma unroll
        for (int c_ = 0; c_ < 4; ++c_) acc[a_][c_] = 0ull;

    #pragma unroll
    for (int mm = 0; mm < 8; ++mm) {
        const int m = mg + mm * 4;
        u64 A[4][2], B[4][2];
        #pragma unroll
        for (int d = 0; d < 4; ++d) {
            float4 av = a_dup[m][i0 + d];
            A[d][0] = pk2(av.x, av.y); A[d][1] = pk2(av.z, av.w);
            float4 bv = b_ns[m][j0 + d];
            B[d][0] = pk2(bv.x, bv.y); B[d][1] = pk2(bv.z, bv.w);
        }
        #pragma unroll
        for (int di = 0; di < 4; ++di)
            #pragma unroll
            for (int dj = 0; dj < 4; ++dj) {
                acc[di][dj] = ffma2(A[di][0], B[dj][0], acc[di][dj]);
                acc[di][dj] = ffma2(A[di][1], B[dj][1], acc[di][dj]);
            }
    }
    __syncthreads();

    // cross-m-group reduce: groups 1..3 spill, group 0 sums + writes tile
    if (mg > 0) {
        u64* dst = red + ((mg - 1) * 64 + t64) * 16;
        #pragma unroll
        for (int di = 0; di < 4; ++di)
            #pragma unroll
            for (int dj = 0; dj < 4; ++dj) dst[di * 4 + dj] = acc[di][dj];
    }
    __syncthreads();
    if (mg == 0) {
        #pragma unroll
        for (int g = 0; g < 3; ++g) {
            const u64* srcp = red + (g * 64 + t64) * 16;
            #pragma unroll
            for (int di = 0; di < 4; ++di)
                #pragma unroll
                for (int dj = 0; dj < 4; ++dj)
                    acc[di][dj] = fadd2(acc[di][dj], srcp[di * 4 + dj]);
        }
        float4* gout = reinterpret_cast<float4*>(g_scratch + b * (R * R));
        #pragma unroll
        for (int di = 0; di < 4; ++di) {
            float2 c0 = upk2(acc[di][0]), c1 = upk2(acc[di][1]);
            float2 c2 = upk2(acc[di][2]), c3 = upk2(acc[di][3]);
            int base = ((i0 + di) * R + j0) >> 1;
            gout[base]     = make_float4(c0.x, c0.y, c1.x, c1.y);
            gout[base + 1] = make_float4(c2.x, c2.y, c3.x, c3.y);
        }
    }
}

// ---------------------------------------------------------------------------
// K1.5: parallel fold 512 tiles -> 64 tiles. Block r sums tiles [8r, 8r+8).
// 256 threads, 2 float4 per thread per tile. Fixed order -> deterministic.
// ---------------------------------------------------------------------------
__global__ void __launch_bounds__(256) reduce_kernel() {
    const int tid = threadIdx.x;
    const int r   = blockIdx.x;
    const float4* src = (const float4*)(g_scratch) + (size_t)r * 8 * 512;
    float4* dst = (float4*)(g_red) + (size_t)r * 512;

    #pragma unroll
    for (int h = 0; h < 2; ++h) {
        int e = tid + h * 256;
        float4 s = src[e];
        #pragma unroll
        for (int b = 1; b < 8; ++b) {
            float4 a = src[b * 512 + e];
            s.x += a.x; s.y += a.y; s.z += a.z; s.w += a.w;
        }
        dst[e] = s;
    }
}

// ---------------------------------------------------------------------------
// K2: single block, 1024 threads.
//   Phase A: reduce 64 tiles (512KB) -> smem A
//   Phase B: (p,q)-parallel Cholesky
//   Phase C: back-substitution L^H w = e_j, one warp per column
// ---------------------------------------------------------------------------
__global__ void solve_kernel() {
    __shared__ float2 As[R * 33];
    __shared__ float4 red[2][512];
    __shared__ float2 colbuf[2][R];

    const int tid = threadIdx.x;
    const int p = tid >> 5, q = tid & 31;

    // ---- Phase A ----
    {
        const int pairIdx = tid & 511;
        const int half    = tid >> 9;
        const float4* src = (const float4*)g_red;
        float4 s = make_float4(0.f, 0.f, 0.f, 0.f);
        #pragma unroll 8
        for (int bb = 0; bb < NBR / 2; ++bb) {
            int b = half * (NBR / 2) + bb;
            float4 a = src[b * 512 + pairIdx];
            s.x += a.x; s.y += a.y; s.z += a.z; s.w += a.w;
        }
        red[half][pairIdx] = s;
    }
    __syncthreads();
    if (tid < 512) {
        float4 u = red[0][tid], v = red[1][tid];
        int e0 = tid * 2, e1 = e0 + 1;
        As[(e0 >> 5) * 33 + (e0 & 31)] = make_float2(u.x + v.x, u.y + v.y);
        As[(e1 >> 5) * 33 + (e1 & 31)] = make_float2(u.z + v.z, u.w + v.w);
    }
    __syncthreads();

    // ---- Phase B: parallel Cholesky ----
    float2 a = As[p * 33 + q];
    for (int k = 0; k < R; ++k) {
        if (q == k) colbuf[k & 1][p] = a;
        __syncthreads();
        float dkk = colbuf[k & 1][k].x;
        float rd  = rsqrtf(dkk + EPSF);
        float d   = (dkk + EPSF) * rd;
        float2 cp = colbuf[k & 1][p];
        float2 cq = colbuf[k & 1][q];
        float2 lp = make_float2(cp.x * rd, cp.y * rd);
        float2 lq = make_float2(cq.x * rd, cq.y * rd);
        if (p > k && q > k) {
            a.x -= lp.x * lq.x + lp.y * lq.y;
            a.y -= lp.y * lq.x - lp.x * lq.y;
        }
        if (q == k) {
            if (p == k)      a = make_float2(d, 0.f);
            else if (p > k)  a = lp;
        }
    }
    __syncthreads();
    As[p * 33 + q] = a;
    __syncthreads();

    // ---- Phase C: warp j solves L^H w = e_j -> W = L^{-H} ----
    {
        const int j    = tid >> 5;
        const int lane = tid & 31;
        const float invd = 1.0f / As[lane * 33 + lane].x;

        float2 accw = make_float2(0.f, 0.f);
        float2 wp   = make_float2(0.f, 0.f);

        for (int qq = j; qq >= 0; --qq) {
            float cre = (((lane == j) ? 1.f : 0.f) - accw.x) * invd;
            float cim = (-accw.y) * invd;
            float wr = __shfl_sync(0xffffffffu, cre, qq);
            float wi = __shfl_sync(0xffffffffu, cim, qq);
            if (lane == qq) { wp.x = wr; wp.y = wi; }

            float2 lqp = As[qq * 33 + lane];
            if (lane < qq) {
                accw.x += lqp.x * wr + lqp.y * wi;
                accw.y += lqp.x * wi - lqp.y * wr;
            }
        }
        g_W[lane * R + j] = wp;   // W[k][j]
    }
}

// ---------------------------------------------------------------------------
// K3: Q = X * W. 512 blocks x 256 threads; each warp does 4 rows.
// Lane j computes out[m][j]; W column j register-resident; x row broadcast
// via shfl; k-loop fully unrolled (independent accumulator FMAs).
// ---------------------------------------------------------------------------
__global__ void __launch_bounds__(256) apply_kernel(const float2* __restrict__ x,
                                                    float2* __restrict__ out) {
    const int lane = threadIdx.x & 31;
    const int gw   = (blockIdx.x * blockDim.x + threadIdx.x) >> 5;

    float wr[R], wi[R];
    #pragma unroll
    for (int k = 0; k < R; ++k) {
        float2 wv = g_W[k * R + lane];
        wr[k] = wv.x; wi[k] = wv.y;
    }

    const int m0 = gw * 4;
    #pragma unroll
    for (int r = 0; r < 4; ++r) {
        int m = m0 + r;
        float2 v = x[m * R + lane];
        float or_ = 0.f, oi_ = 0.f;
        #pragma unroll
        for (int k = 0; k < R; ++k) {
            float ar = __shfl_sync(0xffffffffu, v.x, k);
            float ai = __shfl_sync(0xffffffffu, v.y, k);
            or_ += ar * wr[k] - ai * wi[k];
            oi_ += ar * wi[k] + ai * wr[k];
        }
        out[m * R + lane] = make_float2(or_, oi_);
    }
}

// ---------------------------------------------------------------------------
extern "C" void kernel_launch(void* const* d_in, const int* in_sizes, int n_in,
                              void* d_out, int out_size) {
    const float2* x  = (const float2*)d_in[0];
    float2* out      = (float2*)d_out;

    gram_kernel<<<NBG, 256>>>(x);
    reduce_kernel<<<NBR, 256>>>();
    solve_kernel<<<1, 1024>>>();
    apply_kernel<<<512, 256>>>(x, out);
}